// round 12
// baseline (speedup 1.0000x reference)
#include <cuda_runtime.h>
#include <math.h>

#define EMB    4096
#define DIM    4096
#define TPREV  8192
#define TTOT   (TPREV + 1)     // 8193
#define NCHUNK 64
#define CHUNK  (EMB / NCHUNK)  // 64
#define TPAD   8224            // padded stride for partials (mult of 32)

// Scratch (device globals — no allocation allowed)
__device__ __align__(16) float g_q[DIM];
__device__ __align__(16) float g_k[DIM];
__device__ __align__(16) float g_v[DIM];
__device__ __align__(16) float g_part[NCHUNK * TPAD];
__device__ __align__(16) float g_a[TTOT + 3];

__device__ __forceinline__ float warp_red(float v) {
#pragma unroll
    for (int off = 16; off; off >>= 1)
        v += __shfl_xor_sync(0xffffffffu, v, off);
    return v;
}

// ---------------------------------------------------------------------------
// Kernel 1: q/k/v = W{q,k,v} @ x — ONE warp per output row. 2 batches of
// 16 front-grouped streaming W loads (__ldcs); x consumed from L1 per-FMA.
// 12288 warps -> 1536 blocks of 256. Reg budget 85 (launch_bounds 256,3).
// ---------------------------------------------------------------------------
__global__ void __launch_bounds__(256, 3)
qkv_kernel(const float* __restrict__ x,
           const float* __restrict__ Wq,
           const float* __restrict__ Wk,
           const float* __restrict__ Wv) {
    int gw   = (blockIdx.x * blockDim.x + threadIdx.x) >> 5;
    int lane = threadIdx.x & 31;
    int which = gw >> 12;
    int row   = gw & (DIM - 1);

    const float* W = (which == 0) ? Wq : (which == 1) ? Wk : Wv;
    const float4* wr = reinterpret_cast<const float4*>(W) + (size_t)row * (EMB / 4);
    const float4* xv = reinterpret_cast<const float4*>(x);

    float acc = 0.0f;
#pragma unroll
    for (int b = 0; b < 2; b++) {            // 2 batches of 16 float4 per lane
        float4 w[16];
#pragma unroll
        for (int j = 0; j < 16; j++)         // 16 DRAM loads front-batched
            w[j] = __ldcs(&wr[lane + (b * 16 + j) * 32]);
#pragma unroll
        for (int j = 0; j < 16; j++) {       // x from L1, consumed immediately
            float4 xx = __ldg(&xv[lane + (b * 16 + j) * 32]);
            acc += w[j].x * xx.x + w[j].y * xx.y + w[j].z * xx.z + w[j].w * xx.w;
        }
    }
    acc = warp_red(acc);

    if (lane == 0) {
        float* dst = (which == 0) ? g_q : (which == 1) ? g_k : g_v;
        dst[row] = acc;
    }
}

// ---------------------------------------------------------------------------
// Kernel 2: partial scores. Grid (8, 64), block 256 -> 4096 warps.
// Thread owns one float4 along t, chunk of 64 d; unroll 16 front-batches
// independent streaming LDG.128. Deterministic partials. Tail in kernel 3.
// ---------------------------------------------------------------------------
__global__ void __launch_bounds__(256, 4)
score_partial_kernel(const float* __restrict__ Kc) {
    __shared__ float sq[CHUNK];
    int c  = blockIdx.y;
    int d0 = c * CHUNK;
    if (threadIdx.x < CHUNK)
        sq[threadIdx.x] = g_q[d0 + threadIdx.x];
    __syncthreads();

    int t4 = blockIdx.x * blockDim.x + threadIdx.x;   // 0..2047
    const float4* col = reinterpret_cast<const float4*>(Kc) +
                        (size_t)d0 * (TPREV / 4) + t4;

    float4 acc = make_float4(0.f, 0.f, 0.f, 0.f);
#pragma unroll 16
    for (int d = 0; d < CHUNK; d++) {
        float4 kk = __ldcs(&col[(size_t)d * (TPREV / 4)]);
        float  s  = sq[d];
        acc.x += s * kk.x; acc.y += s * kk.y;
        acc.z += s * kk.z; acc.w += s * kk.w;
    }
    reinterpret_cast<float4*>(g_part + c * TPAD)[t4] = acc;
}

// ---------------------------------------------------------------------------
// Kernel 3: reduce partials -> sigmoid scores. 33 blocks of 256:
// blocks 0..31 reduce over 64 chunks; block 32 computes the t=8192 tail.
// ---------------------------------------------------------------------------
__global__ void sigmoid_kernel() {
    if (blockIdx.x < 32) {
        int t = blockIdx.x * 256 + threadIdx.x;
        float s = 0.0f;
#pragma unroll
        for (int c = 0; c < NCHUNK; c++)
            s += g_part[c * TPAD + t];
        s *= 0.015625f;  // 1/sqrt(4096)
        g_a[t] = 1.0f / (1.0f + expf(-s));
    } else {
        __shared__ float red[256];
        float s = 0.0f;
#pragma unroll
        for (int j = 0; j < 16; j++) {
            int d = threadIdx.x + 256 * j;
            s += g_q[d] * g_k[d];
        }
        red[threadIdx.x] = s;
        __syncthreads();
#pragma unroll
        for (int w = 128; w >= 1; w >>= 1) {
            if (threadIdx.x < w) red[threadIdx.x] += red[threadIdx.x + w];
            __syncthreads();
        }
        if (threadIdx.x == 0) {
            float v = red[0] * 0.015625f;
            g_a[TPREV] = 1.0f / (1.0f + expf(-v));
        }
    }
}

// ---------------------------------------------------------------------------
// Kernel 4: z[d] = V_cache[d,:] . a[0:T] + v[d]*a[T].
// ONE warp per row; 4 batches of 16 front-grouped streaming V loads (__ldcs);
// a consumed from L1 per-FMA. 4096 warps -> 512 blocks of 256.
// Reg budget 85 (launch_bounds 256,3).
// ---------------------------------------------------------------------------
__global__ void __launch_bounds__(256, 3)
out_kernel(const float* __restrict__ Vc, float* __restrict__ out) {
    int warp = threadIdx.x >> 5;
    int lane = threadIdx.x & 31;
    int row  = blockIdx.x * 8 + warp;

    const float4* vr = reinterpret_cast<const float4*>(Vc) + (size_t)row * (TPREV / 4);
    const float4* av = reinterpret_cast<const float4*>(g_a);

    float acc = 0.0f;
#pragma unroll
    for (int b = 0; b < 4; b++) {            // 4 batches of 16 float4 per lane
        float4 v[16];
#pragma unroll
        for (int j = 0; j < 16; j++)         // 16 DRAM loads front-batched
            v[j] = __ldcs(&vr[lane + (b * 16 + j) * 32]);
#pragma unroll
        for (int j = 0; j < 16; j++) {       // a from L1, consumed immediately
            float4 a = __ldg(&av[lane + (b * 16 + j) * 32]);
            acc += v[j].x * a.x + v[j].y * a.y + v[j].z * a.z + v[j].w * a.w;
        }
    }
    acc = warp_red(acc);

    if (lane == 0)
        out[row] = acc + g_v[row] * g_a[TPREV];
}

// ---------------------------------------------------------------------------
extern "C" void kernel_launch(void* const* d_in, const int* in_sizes, int n_in,
                              void* d_out, int out_size) {
    const float* x  = (const float*)d_in[0];
    const float* Wq = (const float*)d_in[1];
    const float* Wk = (const float*)d_in[2];
    const float* Wv = (const float*)d_in[3];
    const float* Kc = (const float*)d_in[4];
    const float* Vc = (const float*)d_in[5];
    float* out = (float*)d_out;

    qkv_kernel<<<(3 * DIM) / 8, 256>>>(x, Wq, Wk, Wv);

    dim3 sg(TPREV / (256 * 4), NCHUNK);          // (8, 64)
    score_partial_kernel<<<sg, 256>>>(Kc);

    sigmoid_kernel<<<33, 256>>>();

    out_kernel<<<DIM / 8, 256>>>(Vc, out);
}